// round 8
// baseline (speedup 1.0000x reference)
#include <cuda_runtime.h>

#define GAMMA_ 10.0f
#define EPS_   1e-6f

constexpr int Cn = 1000;  // classes
constexpr int Bn = 128;   // batch
constexpr int SPLITK = 2;

// ---------------- device scratch ----------------
__device__ float g_npart[8][1024];         // norm partials: idx = z*4 + h
__device__ float g_P[SPLITK][256][1024];   // split-K slabs: rows 0..127 logits, 128..255 gram

// ---------------- k2: tf32 mma.sync GEMM, CTA 64x64, 4 warps, split-K=2 ----
// blockIdx.y (mb): 0,1 = activation row-halves; 2,3 = gram rows (direct W-column gather);
//                  4,5 = column-norm partial lanes
constexpr int PA = 36;   // (gid*36 + q) % 32 = gid*4+q : bijective -> conflict-free A frags
constexpr int PB = 72;   // (q*72 + gid) % 32 = q*8+gid : bijective -> conflict-free B frags

__global__ __launch_bounds__(128) void k2_gemm(const float* __restrict__ A,
                                               const float* __restrict__ W,
                                               const int* __restrict__ targets,
                                               float* __restrict__ out) {
    const int tid = threadIdx.x;
    const int mb = blockIdx.y;
    const int kb = blockIdx.z;

    if (mb >= 4) {
        // column-norm partials, coalesced over c; overlaps with GEMM blocks
        const int item = blockIdx.x * 128 + tid;      // 0..2047
        const int c = item & 1023;
        const int h = (mb - 4) * 2 + (item >> 10);    // 0..3
        if (c < Cn) {
            const int r0 = kb * 512 + h * 128;
            float acc = 0.0f;
#pragma unroll 8
            for (int j = 0; j < 128; ++j) {
                float w = W[(r0 + j) * Cn + c];
                acc = fmaf(w, w, acc);
            }
            g_npart[kb * 4 + h][c] = acc;
        }
        if (mb == 4 && blockIdx.x == 0 && kb == 0 && tid == 0) out[0] = 0.0f;
        return;
    }

    __shared__ __align__(16) unsigned As[2][64][PA];
    __shared__ __align__(16) unsigned Bs[2][32][PB];
    __shared__ int s_t[64];

    const int lane = tid & 31, wid = tid >> 5;
    const int wm = wid & 1, wn = wid >> 1;            // warp grid 2 x 2
    const int n0 = blockIdx.x * 64;
    const int kbase = kb * 512;
    const bool gatherA = (mb >= 2);
    const float* Asrc = gatherA ? nullptr : (A + (size_t)mb * 64 * 1024);

    if (tid < 64) s_t[tid] = gatherA ? targets[(mb - 2) * 64 + tid] : 0;
    __syncthreads();

    float acc[2][4][4];
#pragma unroll
    for (int i = 0; i < 2; ++i)
#pragma unroll
        for (int j = 0; j < 4; ++j)
#pragma unroll
            for (int k = 0; k < 4; ++k) acc[i][j][k] = 0.f;

    uint4 pa[4], pb[4];
    auto ldchunk = [&](int kc) {
        const int k0 = kbase + kc * 32;
        if (!gatherA) {
#pragma unroll
            for (int p = 0; p < 4; ++p) {
                int i = tid + 128 * p;                // 512 uint4 granules (64x32)
                int row = i >> 3, kq = i & 7;
                pa[p] = *(const uint4*)(Asrc + row * 1024 + k0 + kq * 4);
            }
        } else {
#pragma unroll
            for (int p = 0; p < 4; ++p) {
                int i = tid + 128 * p;
                int row = i >> 3, kq = i & 7;
                const float* base = W + (size_t)(k0 + kq * 4) * Cn + s_t[row];
                pa[p].x = __float_as_uint(base[0]);
                pa[p].y = __float_as_uint(base[Cn]);
                pa[p].z = __float_as_uint(base[2 * Cn]);
                pa[p].w = __float_as_uint(base[3 * Cn]);
            }
        }
#pragma unroll
        for (int p = 0; p < 4; ++p) {
            int i = tid + 128 * p;                    // 512 uint4 granules (32x64)
            int r = i >> 4, nq = i & 15;
            int gc = n0 + nq * 4;
            pb[p] = (gc < Cn) ? *(const uint4*)(W + (size_t)(k0 + r) * Cn + gc)
                              : make_uint4(0u, 0u, 0u, 0u);
        }
    };
    auto stchunk = [&](int bf) {
#pragma unroll
        for (int p = 0; p < 4; ++p) {
            int i = tid + 128 * p;
            int row = i >> 3, kq = i & 7;
            *(uint4*)&As[bf][row][kq * 4] = pa[p];
        }
#pragma unroll
        for (int p = 0; p < 4; ++p) {
            int i = tid + 128 * p;
            int r = i >> 4, nq = i & 15;
            *(uint4*)&Bs[bf][r][nq * 4] = pb[p];
        }
    };

    ldchunk(0);
    stchunk(0);
    __syncthreads();

    for (int ch = 0; ch < 16; ++ch) {
        if (ch < 15) ldchunk(ch + 1);
        const int bf = ch & 1;
        const int gid = lane >> 2, q = lane & 3;
#pragma unroll
        for (int ks = 0; ks < 4; ++ks) {
            const int col = ks * 8 + q;
            unsigned a[2][4], b[4][2];
#pragma unroll
            for (int mf = 0; mf < 2; ++mf) {
                int r = wm * 32 + mf * 16 + gid;
                a[mf][0] = As[bf][r][col];
                a[mf][1] = As[bf][r + 8][col];
                a[mf][2] = As[bf][r][col + 4];
                a[mf][3] = As[bf][r + 8][col + 4];
            }
#pragma unroll
            for (int nf = 0; nf < 4; ++nf) {
                int nn = wn * 32 + nf * 8 + gid;
                b[nf][0] = Bs[bf][col][nn];
                b[nf][1] = Bs[bf][col + 4][nn];
            }
#pragma unroll
            for (int mf = 0; mf < 2; ++mf)
#pragma unroll
                for (int nf = 0; nf < 4; ++nf)
                    asm volatile(
                        "mma.sync.aligned.m16n8k8.row.col.f32.tf32.tf32.f32 "
                        "{%0,%1,%2,%3},{%4,%5,%6,%7},{%8,%9},{%0,%1,%2,%3};"
                        : "+f"(acc[mf][nf][0]), "+f"(acc[mf][nf][1]),
                          "+f"(acc[mf][nf][2]), "+f"(acc[mf][nf][3])
                        : "r"(a[mf][0]), "r"(a[mf][1]), "r"(a[mf][2]), "r"(a[mf][3]),
                          "r"(b[nf][0]), "r"(b[nf][1]));
        }
        if (ch < 15) {
            __syncthreads();
            stchunk((ch + 1) & 1);
            __syncthreads();
        }
    }

    // epilogue: plain stores into this split-K slab
    const int m0 = mb * 64, gid = lane >> 2, q = lane & 3;
#pragma unroll
    for (int mf = 0; mf < 2; ++mf) {
        int row = m0 + wm * 32 + mf * 16 + gid;
#pragma unroll
        for (int nf = 0; nf < 4; ++nf) {
            int coln = n0 + wn * 32 + nf * 8 + 2 * q;
            *(float2*)&g_P[kb][row][coln]     = make_float2(acc[mf][nf][0], acc[mf][nf][1]);
            *(float2*)&g_P[kb][row + 8][coln] = make_float2(acc[mf][nf][2], acc[mf][nf][3]);
        }
    }
}

// ---------------- k3: per-row max violation, mean into out ----------------
__global__ __launch_bounds__(1024) void k3_loss(const float* __restrict__ bvec,
                                                const int* __restrict__ targets,
                                                float* __restrict__ out) {
    const int i = blockIdx.x;
    const int c = threadIdx.x;
    const int t = targets[i];
    __shared__ float s_corr, s_nt;
    __shared__ float red[32];

    float nc = 0.0f;
    if (c < Cn) {
#pragma unroll
        for (int p = 0; p < 8; ++p) nc += g_npart[p][c];
    }

    if (c == 0) {
        float sc = bvec[t], nt = 0.0f;
#pragma unroll
        for (int s = 0; s < SPLITK; ++s) sc += g_P[s][i][t];
#pragma unroll
        for (int p = 0; p < 8; ++p) nt += g_npart[p][t];
        s_corr = sc;
        s_nt = nt;
    }
    __syncthreads();

    float v = 0.0f;
    if (c < Cn && c != t) {
        float lg = bvec[c], gr = 0.0f;
#pragma unroll
        for (int s = 0; s < SPLITK; ++s) {
            lg += g_P[s][i][c];
            gr += g_P[s][i + 128][c];
        }
        float ss = nc + s_nt - 2.0f * gr;
        float dn = sqrtf(ss + EPS_) + EPS_;
        v = fmaxf(0.0f, GAMMA_ + (lg - s_corr) / dn);
    }
#pragma unroll
    for (int o = 16; o; o >>= 1) v = fmaxf(v, __shfl_xor_sync(~0u, v, o));
    if ((c & 31) == 0) red[c >> 5] = v;
    __syncthreads();
    if (c < 32) {
        float r = red[c];
#pragma unroll
        for (int o = 16; o; o >>= 1) r = fmaxf(r, __shfl_xor_sync(~0u, r, o));
        if (c == 0) atomicAdd(out, r * (1.0f / 128.0f));
    }
}

// ---------------- launch ----------------
extern "C" void kernel_launch(void* const* d_in, const int* in_sizes, int n_in,
                              void* d_out, int out_size) {
    const float* A = (const float*)d_in[0];        // [128,1024]
    const float* W = (const float*)d_in[1];        // [1024,1000]
    const float* b = (const float*)d_in[2];        // [1000]
    const int* targets = (const int*)d_in[3];      // [128]
    float* out = (float*)d_out;

    k2_gemm<<<dim3(16, 6, SPLITK), 128>>>(A, W, targets, out);
    k3_loss<<<Bn, 1024>>>(b, targets, out);
}

// round 9
// speedup vs baseline: 1.4372x; 1.4372x over previous
#include <cuda_runtime.h>

#define GAMMA_ 10.0f
#define EPS_   1e-6f

constexpr int Cn = 1000;  // classes
constexpr int Bn = 128;   // batch
constexpr int SPLITK = 2;

// ---------------- device scratch ----------------
__device__ float g_U[128 * 1024];          // gathered target columns W[:,t_i]
__device__ float g_npart[8][1024];         // column-norm partials (128-row slabs)
__device__ float g_norm[1024];             // reduced column norms
__device__ float g_P[SPLITK][256][1024];   // split-K slabs: rows 0..127 logits, 128..255 gram

// ---------------- k1: coalesced gather-through-smem + norm partials ----------------
// blocks 0..127 : stream 8 W-rows through smem, extract target columns -> g_U (coalesced)
// blocks 128..159: norm partials, h=(b-128)>>2 row-slab, q=(b-128)&3 column quarter
__global__ __launch_bounds__(256) void k1_fused(const float* __restrict__ W,
                                                const int* __restrict__ targets) {
    const int bid = blockIdx.x, tid = threadIdx.x;
    if (bid < 128) {
        __shared__ float srow[8][1000];
        __shared__ int s_t[128];
        const int k0 = bid * 8;
        if (tid < 128) s_t[tid] = targets[tid];
#pragma unroll
        for (int r = 0; r < 8; ++r)
            for (int c = tid; c < Cn; c += 256)
                srow[r][c] = W[(k0 + r) * Cn + c];
        __syncthreads();
        const int i = tid >> 1, half = tid & 1;
        const int t = s_t[i];
        float4 v;
        v.x = srow[half * 4 + 0][t];
        v.y = srow[half * 4 + 1][t];
        v.z = srow[half * 4 + 2][t];
        v.w = srow[half * 4 + 3][t];
        *(float4*)&g_U[i * 1024 + k0 + half * 4] = v;
    } else {
        const int h = (bid - 128) >> 2, q = (bid - 128) & 3;
        const int c = q * 256 + tid;
        float acc = 0.0f;
        if (c < Cn) {
            const int r0 = h * 128;
#pragma unroll 8
            for (int j = 0; j < 128; ++j) {
                float w = W[(r0 + j) * Cn + c];
                acc = fmaf(w, w, acc);
            }
        }
        g_npart[h][c] = acc;
    }
}

// ---------------- k2: tf32 mma.sync GEMM, CTA 64x64, 4 warps, split-K=2 ----
// blockIdx.y (mb): 0,1 = A row-halves; 2,3 = U row-halves; 4 = norm reduce + zero out
constexpr int PA = 36;   // conflict-free A frag loads
constexpr int PB = 72;   // conflict-free B frag loads

__global__ __launch_bounds__(128) void k2_gemm(const float* __restrict__ A,
                                               const float* __restrict__ W,
                                               float* __restrict__ out) {
    const int tid = threadIdx.x;
    const int mb = blockIdx.y;
    const int kb = blockIdx.z;

    if (mb == 4) {
        if (kb == 0) {
            if (blockIdx.x < 8) {
                const int c = blockIdx.x * 128 + tid;
                float s = 0.0f;
#pragma unroll
                for (int p = 0; p < 8; ++p) s += g_npart[p][c];
                g_norm[c] = s;
            } else if (blockIdx.x == 8 && tid == 0) {
                out[0] = 0.0f;
            }
        }
        return;
    }

    __shared__ __align__(16) unsigned As[2][64][PA];
    __shared__ __align__(16) unsigned Bs[2][32][PB];

    const int lane = tid & 31, wid = tid >> 5;
    const int wm = wid & 1, wn = wid >> 1;
    const int n0 = blockIdx.x * 64;
    const float* Asrc = (mb < 2) ? (A + (size_t)mb * 64 * 1024)
                                 : (g_U + (size_t)(mb - 2) * 64 * 1024);
    const int kbase = kb * 512;

    float acc[2][4][4];
#pragma unroll
    for (int i = 0; i < 2; ++i)
#pragma unroll
        for (int j = 0; j < 4; ++j)
#pragma unroll
            for (int k = 0; k < 4; ++k) acc[i][j][k] = 0.f;

    uint4 pa[4], pb[4];
    auto ldchunk = [&](int kc) {
        const int k0 = kbase + kc * 32;
#pragma unroll
        for (int p = 0; p < 4; ++p) {
            int i = tid + 128 * p;
            int row = i >> 3, kq = i & 7;
            pa[p] = *(const uint4*)(Asrc + row * 1024 + k0 + kq * 4);
            int r = i >> 4, nq = i & 15;
            int gc = n0 + nq * 4;
            pb[p] = (gc < Cn) ? *(const uint4*)(W + (size_t)(k0 + r) * Cn + gc)
                              : make_uint4(0u, 0u, 0u, 0u);
        }
    };
    auto stchunk = [&](int bf) {
#pragma unroll
        for (int p = 0; p < 4; ++p) {
            int i = tid + 128 * p;
            int row = i >> 3, kq = i & 7;
            *(uint4*)&As[bf][row][kq * 4] = pa[p];
            int r = i >> 4, nq = i & 15;
            *(uint4*)&Bs[bf][r][nq * 4] = pb[p];
        }
    };

    ldchunk(0);
    stchunk(0);
    __syncthreads();

    for (int ch = 0; ch < 16; ++ch) {
        if (ch < 15) ldchunk(ch + 1);
        const int bf = ch & 1;
        const int gid = lane >> 2, q = lane & 3;
#pragma unroll
        for (int ks = 0; ks < 4; ++ks) {
            const int col = ks * 8 + q;
            unsigned a[2][4], b[4][2];
#pragma unroll
            for (int mf = 0; mf < 2; ++mf) {
                int r = wm * 32 + mf * 16 + gid;
                a[mf][0] = As[bf][r][col];
                a[mf][1] = As[bf][r + 8][col];
                a[mf][2] = As[bf][r][col + 4];
                a[mf][3] = As[bf][r + 8][col + 4];
            }
#pragma unroll
            for (int nf = 0; nf < 4; ++nf) {
                int nn = wn * 32 + nf * 8 + gid;
                b[nf][0] = Bs[bf][col][nn];
                b[nf][1] = Bs[bf][col + 4][nn];
            }
#pragma unroll
            for (int mf = 0; mf < 2; ++mf)
#pragma unroll
                for (int nf = 0; nf < 4; ++nf)
                    asm volatile(
                        "mma.sync.aligned.m16n8k8.row.col.f32.tf32.tf32.f32 "
                        "{%0,%1,%2,%3},{%4,%5,%6,%7},{%8,%9},{%0,%1,%2,%3};"
                        : "+f"(acc[mf][nf][0]), "+f"(acc[mf][nf][1]),
                          "+f"(acc[mf][nf][2]), "+f"(acc[mf][nf][3])
                        : "r"(a[mf][0]), "r"(a[mf][1]), "r"(a[mf][2]), "r"(a[mf][3]),
                          "r"(b[nf][0]), "r"(b[nf][1]));
        }
        if (ch < 15) {
            __syncthreads();
            stchunk((ch + 1) & 1);
            __syncthreads();
        }
    }

    const int m0 = mb * 64, gid = lane >> 2, q = lane & 3;
#pragma unroll
    for (int mf = 0; mf < 2; ++mf) {
        int row = m0 + wm * 32 + mf * 16 + gid;
#pragma unroll
        for (int nf = 0; nf < 4; ++nf) {
            int coln = n0 + wn * 32 + nf * 8 + 2 * q;
            *(float2*)&g_P[kb][row][coln]     = make_float2(acc[mf][nf][0], acc[mf][nf][1]);
            *(float2*)&g_P[kb][row + 8][coln] = make_float2(acc[mf][nf][2], acc[mf][nf][3]);
        }
    }
}

// ---------------- k3: per-row max violation (4 classes/thread), mean into out ----
__global__ __launch_bounds__(256) void k3_loss(const float* __restrict__ bvec,
                                               const int* __restrict__ targets,
                                               float* __restrict__ out) {
    const int i = blockIdx.x;
    const int tid = threadIdx.x;
    const int t = targets[i];
    __shared__ float s_corr, s_nt;
    __shared__ float red[8];

    if (tid == 0) {
        s_corr = g_P[0][i][t] + g_P[1][i][t] + bvec[t];
        s_nt = g_norm[t];
    }
    __syncthreads();
    const float corr = s_corr, nt = s_nt;

    float vmax = 0.0f;
#pragma unroll
    for (int j = 0; j < 4; ++j) {
        const int c = tid + j * 256;
        if (c < Cn && c != t) {
            float lg = g_P[0][i][c] + g_P[1][i][c] + bvec[c];
            float gr = g_P[0][i + 128][c] + g_P[1][i + 128][c];
            float ss = g_norm[c] + nt - 2.0f * gr;
            float dn = sqrtf(ss + EPS_) + EPS_;
            float v = fmaxf(0.0f, GAMMA_ + (lg - corr) / dn);
            vmax = fmaxf(vmax, v);
        }
    }
#pragma unroll
    for (int o = 16; o; o >>= 1) vmax = fmaxf(vmax, __shfl_xor_sync(~0u, vmax, o));
    if ((tid & 31) == 0) red[tid >> 5] = vmax;
    __syncthreads();
    if (tid == 0) {
        float r = red[0];
#pragma unroll
        for (int w = 1; w < 8; ++w) r = fmaxf(r, red[w]);
        atomicAdd(out, r * (1.0f / 128.0f));
    }
}

// ---------------- launch ----------------
extern "C" void kernel_launch(void* const* d_in, const int* in_sizes, int n_in,
                              void* d_out, int out_size) {
    const float* A = (const float*)d_in[0];        // [128,1024]
    const float* W = (const float*)d_in[1];        // [1024,1000]
    const float* b = (const float*)d_in[2];        // [1000]
    const int* targets = (const int*)d_in[3];      // [128]
    float* out = (float*)d_out;

    k1_fused<<<160, 256>>>(W, targets);
    k2_gemm<<<dim3(16, 5, SPLITK), 128>>>(A, W, out);
    k3_loss<<<Bn, 256>>>(b, targets, out);
}

// round 10
// speedup vs baseline: 1.8206x; 1.2668x over previous
#include <cuda_runtime.h>

#define GAMMA_ 10.0f
#define EPS_   1e-6f

constexpr int Cn = 1000;  // classes
constexpr int Bn = 128;   // batch
constexpr int SPLITK = 2;

// ---------------- device scratch ----------------
__device__ float g_U[128 * 1024];          // gathered target columns W[:,t_i]
__device__ float g_npart[32][1024];        // column-norm partials (32-row slabs)
__device__ float g_norm[1024];             // reduced column norms
__device__ float g_P[SPLITK][256][1024];   // split-K slabs: rows 0..127 logits, 128..255 gram

// ---------------- k1: coalesced transpose-gather + norm partials ----------------
// blocks 0..255 : (kc = bid>>2, cc = bid&3) 16-row x 250-col W panel -> smem ->
//                 coalesced 64B writes of target columns into g_U
// blocks 256..383: norm partials, (rc = nb>>2) 32-row slab, (cq = nb&3) column quarter
__global__ __launch_bounds__(256) void k1_prep(const float* __restrict__ W,
                                               const int* __restrict__ targets) {
    const int bid = blockIdx.x, tid = threadIdx.x;
    if (bid < 256) {
        __shared__ float srow[16][250];
        __shared__ int s_t[128];
        const int k0 = (bid >> 2) * 16;
        const int c0 = (bid & 3) * 250;
        if (tid < 128) s_t[tid] = targets[tid];
#pragma unroll
        for (int r = 0; r < 16; ++r)
            if (tid < 250) srow[r][tid] = W[(k0 + r) * Cn + c0 + tid];
        __syncthreads();

        const int lane = tid & 31, wid = tid >> 5;
        const int stream = wid * 2 + (lane >> 4);   // 0..15
        const int sub = lane & 15;                  // k offset within 16-row chunk
#pragma unroll
        for (int rep = 0; rep < 8; ++rep) {
            const int j = stream + rep * 16;        // sample index 0..127
            const int t = s_t[j];
            if (t >= c0 && t < c0 + 250)
                g_U[j * 1024 + k0 + sub] = srow[sub][t - c0];
        }
    } else {
        const int nb = bid - 256;
        const int rc = nb >> 2, cq = nb & 3;
        const int c = cq * 256 + tid;
        if (c < Cn) {
            const int r0 = rc * 32;
            float acc = 0.0f;
#pragma unroll
            for (int j = 0; j < 32; ++j) {
                float w = W[(r0 + j) * Cn + c];
                acc = fmaf(w, w, acc);
            }
            g_npart[rc][c] = acc;
        }
    }
}

// ---------------- k2: tf32 mma.sync GEMM, CTA 64x64, 4 warps, split-K=2 ----
// blockIdx.y (mb): 0,1 = A row-halves; 2,3 = U row-halves; 4 = norm reduce + zero out
constexpr int PA = 36;   // conflict-free A frag loads
constexpr int PB = 72;   // conflict-free B frag loads

__global__ __launch_bounds__(128) void k2_gemm(const float* __restrict__ A,
                                               const float* __restrict__ W,
                                               float* __restrict__ out) {
    const int tid = threadIdx.x;
    const int mb = blockIdx.y;
    const int kb = blockIdx.z;

    if (mb == 4) {
        if (kb == 0) {
            if (blockIdx.x < 8) {
                const int c = blockIdx.x * 128 + tid;
                float s = 0.0f;
#pragma unroll
                for (int p = 0; p < 32; ++p) s += g_npart[p][c];
                g_norm[c] = s;
            } else if (blockIdx.x == 8 && tid == 0) {
                out[0] = 0.0f;
            }
        }
        return;
    }

    __shared__ __align__(16) unsigned As[2][64][PA];
    __shared__ __align__(16) unsigned Bs[2][32][PB];

    const int lane = tid & 31, wid = tid >> 5;
    const int wm = wid & 1, wn = wid >> 1;
    const int n0 = blockIdx.x * 64;
    const float* Asrc = (mb < 2) ? (A + (size_t)mb * 64 * 1024)
                                 : (g_U + (size_t)(mb - 2) * 64 * 1024);
    const int kbase = kb * 512;

    float acc[2][4][4];
#pragma unroll
    for (int i = 0; i < 2; ++i)
#pragma unroll
        for (int j = 0; j < 4; ++j)
#pragma unroll
            for (int k = 0; k < 4; ++k) acc[i][j][k] = 0.f;

    uint4 pa[4], pb[4];
    auto ldchunk = [&](int kc) {
        const int k0 = kbase + kc * 32;
#pragma unroll
        for (int p = 0; p < 4; ++p) {
            int i = tid + 128 * p;
            int row = i >> 3, kq = i & 7;
            pa[p] = *(const uint4*)(Asrc + row * 1024 + k0 + kq * 4);
            int r = i >> 4, nq = i & 15;
            int gc = n0 + nq * 4;
            pb[p] = (gc < Cn) ? *(const uint4*)(W + (size_t)(k0 + r) * Cn + gc)
                              : make_uint4(0u, 0u, 0u, 0u);
        }
    };
    auto stchunk = [&](int bf) {
#pragma unroll
        for (int p = 0; p < 4; ++p) {
            int i = tid + 128 * p;
            int row = i >> 3, kq = i & 7;
            *(uint4*)&As[bf][row][kq * 4] = pa[p];
            int r = i >> 4, nq = i & 15;
            *(uint4*)&Bs[bf][r][nq * 4] = pb[p];
        }
    };

    ldchunk(0);
    stchunk(0);
    __syncthreads();

    for (int ch = 0; ch < 16; ++ch) {
        if (ch < 15) ldchunk(ch + 1);
        const int bf = ch & 1;
        const int gid = lane >> 2, q = lane & 3;
#pragma unroll
        for (int ks = 0; ks < 4; ++ks) {
            const int col = ks * 8 + q;
            unsigned a[2][4], b[4][2];
#pragma unroll
            for (int mf = 0; mf < 2; ++mf) {
                int r = wm * 32 + mf * 16 + gid;
                a[mf][0] = As[bf][r][col];
                a[mf][1] = As[bf][r + 8][col];
                a[mf][2] = As[bf][r][col + 4];
                a[mf][3] = As[bf][r + 8][col + 4];
            }
#pragma unroll
            for (int nf = 0; nf < 4; ++nf) {
                int nn = wn * 32 + nf * 8 + gid;
                b[nf][0] = Bs[bf][col][nn];
                b[nf][1] = Bs[bf][col + 4][nn];
            }
#pragma unroll
            for (int mf = 0; mf < 2; ++mf)
#pragma unroll
                for (int nf = 0; nf < 4; ++nf)
                    asm volatile(
                        "mma.sync.aligned.m16n8k8.row.col.f32.tf32.tf32.f32 "
                        "{%0,%1,%2,%3},{%4,%5,%6,%7},{%8,%9},{%0,%1,%2,%3};"
                        : "+f"(acc[mf][nf][0]), "+f"(acc[mf][nf][1]),
                          "+f"(acc[mf][nf][2]), "+f"(acc[mf][nf][3])
                        : "r"(a[mf][0]), "r"(a[mf][1]), "r"(a[mf][2]), "r"(a[mf][3]),
                          "r"(b[nf][0]), "r"(b[nf][1]));
        }
        if (ch < 15) {
            __syncthreads();
            stchunk((ch + 1) & 1);
            __syncthreads();
        }
    }

    const int m0 = mb * 64, gid = lane >> 2, q = lane & 3;
#pragma unroll
    for (int mf = 0; mf < 2; ++mf) {
        int row = m0 + wm * 32 + mf * 16 + gid;
#pragma unroll
        for (int nf = 0; nf < 4; ++nf) {
            int coln = n0 + wn * 32 + nf * 8 + 2 * q;
            *(float2*)&g_P[kb][row][coln]     = make_float2(acc[mf][nf][0], acc[mf][nf][1]);
            *(float2*)&g_P[kb][row + 8][coln] = make_float2(acc[mf][nf][2], acc[mf][nf][3]);
        }
    }
}

// ---------------- k3: per-row max violation (4 classes/thread), mean into out ----
__global__ __launch_bounds__(256) void k3_loss(const float* __restrict__ bvec,
                                               const int* __restrict__ targets,
                                               float* __restrict__ out) {
    const int i = blockIdx.x;
    const int tid = threadIdx.x;
    const int t = targets[i];
    __shared__ float s_corr, s_nt;
    __shared__ float red[8];

    if (tid == 0) {
        s_corr = g_P[0][i][t] + g_P[1][i][t] + bvec[t];
        s_nt = g_norm[t];
    }
    __syncthreads();
    const float corr = s_corr, nt = s_nt;

    float vmax = 0.0f;
#pragma unroll
    for (int j = 0; j < 4; ++j) {
        const int c = tid + j * 256;
        if (c < Cn && c != t) {
            float lg = g_P[0][i][c] + g_P[1][i][c] + bvec[c];
            float gr = g_P[0][i + 128][c] + g_P[1][i + 128][c];
            float ss = g_norm[c] + nt - 2.0f * gr;
            float dn = sqrtf(ss + EPS_) + EPS_;
            float v = fmaxf(0.0f, GAMMA_ + (lg - corr) / dn);
            vmax = fmaxf(vmax, v);
        }
    }
#pragma unroll
    for (int o = 16; o; o >>= 1) vmax = fmaxf(vmax, __shfl_xor_sync(~0u, vmax, o));
    if ((tid & 31) == 0) red[tid >> 5] = vmax;
    __syncthreads();
    if (tid == 0) {
        float r = red[0];
#pragma unroll
        for (int w = 1; w < 8; ++w) r = fmaxf(r, red[w]);
        atomicAdd(out, r * (1.0f / 128.0f));
    }
}

// ---------------- launch ----------------
extern "C" void kernel_launch(void* const* d_in, const int* in_sizes, int n_in,
                              void* d_out, int out_size) {
    const float* A = (const float*)d_in[0];        // [128,1024]
    const float* W = (const float*)d_in[1];        // [1024,1000]
    const float* b = (const float*)d_in[2];        // [1000]
    const int* targets = (const int*)d_in[3];      // [128]
    float* out = (float*)d_out;

    k1_prep<<<384, 256>>>(W, targets);
    k2_gemm<<<dim3(16, 5, SPLITK), 128>>>(A, W, out);
    k3_loss<<<Bn, 256>>>(b, targets, out);
}